// round 17
// baseline (speedup 1.0000x reference)
#include <cuda_runtime.h>
#include <cuda_fp16.h>
#include <cstdint>
#include <math.h>

#define SEQ   4096
#define DM    2048
#define NH    16
#define NKV   4
#define HDIM  128
#define QW    (NH * HDIM)    /* 2048 */
#define KWW   (NKV * HDIM)   /* 512  */
#define QKVW  (QW + 2 * KWW) /* 3072 */

// ---------------- scratch (device globals; no allocations allowed) ----------
// qkv holds [Q|K|V] fp16; Q,K columns pair-permuted (rope partners adjacent).
__device__ __half g_qkv[SEQ * QKVW];
__device__ __half g_w_hi[QKVW * DM];
__device__ __half g_wo_hi[DM * QW];
__device__ __half g_a_hi[SEQ * QW];

// ---------------- helpers -----------------------------------------------------
__device__ __forceinline__ uint32_t smem_u32(const void* p) {
    uint32_t a;
    asm("{ .reg .u64 t; cvta.to.shared.u64 t, %1; cvt.u32.u64 %0, t; }"
        : "=r"(a) : "l"(p));
    return a;
}

__device__ __forceinline__ void cp16(uint32_t dst, const void* src) {
    asm volatile("cp.async.cg.shared.global [%0], [%1], 16;" :: "r"(dst), "l"(src));
}
#define CP_COMMIT() asm volatile("cp.async.commit_group;" ::: "memory")
#define CP_WAIT(n)  asm volatile("cp.async.wait_group %0;" :: "n"(n) : "memory")

#define LDSM4(r, addr)                                                        \
    asm volatile("ldmatrix.sync.aligned.m8n8.x4.shared.b16 {%0,%1,%2,%3}, [%4];" \
        : "=r"((r)[0]), "=r"((r)[1]), "=r"((r)[2]), "=r"((r)[3]) : "r"(addr))

#define LDSM4T(r, addr)                                                       \
    asm volatile("ldmatrix.sync.aligned.m8n8.x4.trans.shared.b16 {%0,%1,%2,%3}, [%4];" \
        : "=r"((r)[0]), "=r"((r)[1]), "=r"((r)[2]), "=r"((r)[3]) : "r"(addr))

#define MMA16816(d, a, b)                                                     \
    asm volatile("mma.sync.aligned.m16n8k16.row.col.f32.f16.f16.f32 "         \
        "{%0,%1,%2,%3}, {%4,%5,%6,%7}, {%8,%9}, {%0,%1,%2,%3};"               \
        : "+f"((d)[0]), "+f"((d)[1]), "+f"((d)[2]), "+f"((d)[3])              \
        : "r"((a)[0]), "r"((a)[1]), "r"((a)[2]), "r"((a)[3]),                 \
          "r"((b)[0]), "r"((b)[1]))

__device__ __forceinline__ uint32_t hpack2(float x, float y) {
    __half2 hp = __floats2half2_rn(x, y);
    return *reinterpret_cast<uint32_t*>(&hp);
}

// ============================================================================
// fp32 -> fp16 weight conversion (single launch). wq/wk rows pair-permuted:
// within each head, dst_row(d) = 2d (d<64) else 2(d-64)+1.
// ============================================================================
#define N_WQ  (QW  * DM)
#define N_WK  (KWW * DM)
#define N_WV  (KWW * DM)
#define N_WO  (DM  * QW)
#define N_WTOT (N_WQ + N_WK + N_WV + N_WO)

__device__ __forceinline__ int rope_perm_row(int r) {
    int head = r >> 7, rd = r & 127;
    return (head << 7) + ((rd < 64) ? (rd << 1) : (((rd - 64) << 1) | 1));
}

__global__ void conv_w(const float* __restrict__ wq,
                       const float* __restrict__ wk,
                       const float* __restrict__ wv,
                       const float* __restrict__ wo,
                       __half* __restrict__ w_hi,
                       __half* __restrict__ wo_hi)
{
    int i = (blockIdx.x * blockDim.x + threadIdx.x) * 4;
    if (i >= N_WTOT) return;
    const float* src; __half* dst; int off; int permute = 0;
    if (i < N_WQ)                   { src = wq; dst = w_hi;               off = i; permute = 1; }
    else if (i < N_WQ + N_WK)       { src = wk; dst = w_hi + N_WQ;        off = i - N_WQ; permute = 1; }
    else if (i < N_WQ + N_WK + N_WV){ src = wv; dst = w_hi + N_WQ + N_WK; off = i - N_WQ - N_WK; }
    else                            { src = wo; dst = wo_hi;              off = i - N_WQ - N_WK - N_WV; }
    float4 v = *(const float4*)(src + off);
    int doff = off;
    if (permute) {
        int r = off / DM, c = off - r * DM;
        doff = rope_perm_row(r) * DM + c;
    }
    *(uint32_t*)(dst + doff)     = hpack2(v.x, v.y);
    *(uint32_t*)(dst + doff + 2) = hpack2(v.z, v.w);
}

// ============================================================================
// fp16 mma.sync NT GEMM: C = A B^T.
// A_FP32: A is fp32 in gmem, converted in-kernel (LDG -> cvt -> STS pipeline).
// DO_ROPE: apply RoPE in epilogue (Q|K blocks only; pair-permuted layout).
// CTA 128x256, BK=32, 8 warps 2Mx4N (64x64); B 4-stage cp.async;
// A 4 slots (cp.async when fp16, reg-pipeline STS when fp32).
// ============================================================================
#define BK        32
#define LDS_PAD   40
#define A_SLOT_B  (128 * LDS_PAD * 2)          /* 10240 */
#define B_SLOT_B  (256 * LDS_PAD * 2)          /* 20480 */
#define NSTAGE    4
#define A_REG_B   (NSTAGE * A_SLOT_B)          /* 40960 */
#define GEMM_SMEM (A_REG_B + NSTAGE * B_SLOT_B) /* 122880 */

template <typename OutT, bool DO_ROPE, bool A_FP32>
__global__ __launch_bounds__(256, 1) void gemm_f16(
    const void* __restrict__ Araw, const __half* __restrict__ B,
    OutT* __restrict__ C, int N, int K,
    const float* __restrict__ cosT, const float* __restrict__ sinT)
{
    extern __shared__ char smem[];
    const uint32_t sb = smem_u32(smem);
    const int tid  = threadIdx.x;
    const int wid  = tid >> 5, lane = tid & 31;
    const int m0   = blockIdx.y * 128, n0 = blockIdx.x * 256;
    const int wm   = (wid & 1) * 64;
    const int wn   = (wid >> 1) * 64;

    const __half* a16 = (const __half*)Araw + (A_FP32 ? 0 : (size_t)m0 * K);
    const float*  a32 = (const float*)Araw + (size_t)m0 * K;
    const __half* b_p = B + (size_t)n0 * K;

    const int a_row_l = lane & 15;
    const int a_colb  = ((lane >> 4) & 1) << 3;
    const int b_row_l = (lane & 7) + (((lane >> 4) & 1) << 3);
    const int b_colb  = ((lane >> 3) & 1) << 3;

    float d[4][8][4];
#pragma unroll
    for (int i = 0; i < 4; i++)
#pragma unroll
        for (int j = 0; j < 8; j++)
#pragma unroll
            for (int q = 0; q < 4; q++) d[i][j][q] = 0.f;

    const int nk = K / BK;

    float4 areg[4];                      // fp32-A pipeline registers

#define LDG_A(k0) do {                                                        \
    _Pragma("unroll")                                                         \
    for (int it = 0; it < 4; it++) {                                          \
        int idx = tid + it * 256;                                             \
        int r = idx >> 3, c = idx & 7;                                        \
        areg[it] = *(const float4*)(a32 + (size_t)r * K + (k0) + c * 4);      \
    }                                                                         \
} while (0)

#define STS_A(s) do {                                                         \
    uint32_t ab = sb + (uint32_t)(s) * A_SLOT_B;                              \
    _Pragma("unroll")                                                         \
    for (int it = 0; it < 4; it++) {                                          \
        int idx = tid + it * 256;                                             \
        int r = idx >> 3, c = idx & 7;                                        \
        uint32_t off = ab + (uint32_t)(r * LDS_PAD + c * 4) * 2;              \
        uint32_t lo = hpack2(areg[it].x, areg[it].y);                         \
        uint32_t hi = hpack2(areg[it].z, areg[it].w);                         \
        asm volatile("st.shared.v2.b32 [%0], {%1, %2};"                       \
                     :: "r"(off), "r"(lo), "r"(hi) : "memory");               \
    }                                                                         \
} while (0)

#define LOAD_A16(s, k0) do {                                                  \
    uint32_t ab = sb + (uint32_t)(s) * A_SLOT_B;                              \
    _Pragma("unroll")                                                         \
    for (int it = 0; it < 2; it++) {                                          \
        int idx = tid + it * 256;                                             \
        int r = idx >> 2, c = idx & 3;                                        \
        cp16(ab + (uint32_t)(r * LDS_PAD + c * 8) * 2,                        \
             a16 + (size_t)r * K + (k0) + c * 8);                             \
    }                                                                         \
} while (0)

#define LOAD_B(s, k0) do {                                                    \
    uint32_t bb = sb + A_REG_B + (uint32_t)(s) * B_SLOT_B;                    \
    _Pragma("unroll")                                                         \
    for (int it = 0; it < 4; it++) {                                          \
        int idx = tid + it * 256;                                             \
        int r = idx >> 2, c = idx & 3;                                        \
        cp16(bb + (uint32_t)(r * LDS_PAD + c * 8) * 2,                        \
             b_p + (size_t)r * K + (k0) + c * 8);                             \
    }                                                                         \
} while (0)

    // prologue
    if (A_FP32) {
        LDG_A(0);
        LOAD_B(0, 0); CP_COMMIT();
        LOAD_B(1, BK); CP_COMMIT();
        LOAD_B(2, 2 * BK); CP_COMMIT();
    } else {
        LOAD_A16(0, 0);      LOAD_B(0, 0);      CP_COMMIT();
        LOAD_A16(1, BK);     LOAD_B(1, BK);     CP_COMMIT();
        LOAD_A16(2, 2 * BK); LOAD_B(2, 2 * BK); CP_COMMIT();
    }

    for (int kt = 0; kt < nk; kt++) {
        if (kt + 3 < nk) {
            if (A_FP32) { LOAD_B(( kt + 3) % NSTAGE, (kt + 3) * BK); }
            else        { LOAD_A16((kt + 3) % NSTAGE, (kt + 3) * BK);
                          LOAD_B((kt + 3) % NSTAGE, (kt + 3) * BK); }
            CP_COMMIT(); CP_WAIT(3);
        }
        else if (kt + 2 < nk) { CP_WAIT(2); }
        else if (kt + 1 < nk) { CP_WAIT(1); }
        else                  { CP_WAIT(0); }

        if (A_FP32) {
            STS_A(kt % NSTAGE);                  // convert stage kt into smem
            if (kt + 1 < nk) LDG_A((kt + 1) * BK);
        }
        __syncthreads();

        const uint32_t AB = sb + (uint32_t)(kt % NSTAGE) * A_SLOT_B;
        const uint32_t BB = sb + A_REG_B + (uint32_t)(kt % NSTAGE) * B_SLOT_B;

#pragma unroll
        for (int ks = 0; ks < BK; ks += 16) {
            uint32_t ah[4][4];
#pragma unroll
            for (int i = 0; i < 4; i++) {
                uint32_t off = (uint32_t)((wm + 16 * i + a_row_l) * LDS_PAD
                                          + ks + a_colb) * 2;
                LDSM4(ah[i], AB + off);
            }
#pragma unroll
            for (int jp = 0; jp < 4; jp++) {
                uint32_t bh[4];
                uint32_t off = (uint32_t)((wn + 16 * jp + b_row_l) * LDS_PAD
                                          + ks + b_colb) * 2;
                LDSM4(bh, BB + off);
#pragma unroll
                for (int i = 0; i < 4; i++) {
                    MMA16816(d[i][2*jp],   ah[i], bh);
                    MMA16816(d[i][2*jp+1], ah[i], bh + 2);
                }
            }
        }
        __syncthreads();
    }

    const int trow = lane >> 2, tcol = (lane & 3) * 2;
    const bool rope_blk = DO_ROPE && (n0 < QW + KWW);
#pragma unroll
    for (int i = 0; i < 4; i++)
#pragma unroll
        for (int j = 0; j < 8; j++) {
            if (rope_blk) {
                int col   = n0 + wn + 8 * j + tcol;        // even
                int d_idx = (col & 127) >> 1;
                int row0  = m0 + wm + 16 * i + trow;
                float c0 = cosT[row0 * HDIM + d_idx];
                float s0 = sinT[row0 * HDIM + d_idx];
                float c1 = cosT[(row0 + 8) * HDIM + d_idx];
                float s1 = sinT[(row0 + 8) * HDIM + d_idx];
                float x1 = d[i][j][0], x2 = d[i][j][1];
                d[i][j][0] = fmaf(x1, c0, -x2 * s0);
                d[i][j][1] = fmaf(x2, c0,  x1 * s0);
                x1 = d[i][j][2]; x2 = d[i][j][3];
                d[i][j][2] = fmaf(x1, c1, -x2 * s1);
                d[i][j][3] = fmaf(x2, c1,  x1 * s1);
            }
            OutT* p  = C + (size_t)(m0 + wm + 16 * i + trow) * N
                         + (n0 + wn + 8 * j + tcol);
            OutT* p2 = p + (size_t)8 * N;
            if constexpr (sizeof(OutT) == 2) {
                *(uint32_t*)p  = hpack2(d[i][j][0], d[i][j][1]);
                *(uint32_t*)p2 = hpack2(d[i][j][2], d[i][j][3]);
            } else {
                p[0]  = d[i][j][0]; p[1]  = d[i][j][1];
                p2[0] = d[i][j][2]; p2[1] = d[i][j][3];
            }
        }
}

// ============================================================================
// Tensor-core causal flash attention — fp16 operands, fp32 accum,
// fixed-base softmax. Q/K/V read directly from packed qkv (stride QKVW).
// CTA = 64 q-rows x head, 4 warps x 16 rows, 128 threads, Q reg-cached,
// 64-row KV tiles double-buffered; 87 KB smem -> 2 CTAs/SM.
// ============================================================================
#define BQ      64
#define BKV     64
#define FL_STR  136
#define FL_QT   (BQ * FL_STR * 2)
#define FL_KT   (BKV * FL_STR * 2)
#define FL_STG  (2 * FL_KT)
#define FLASH_SMEM (FL_QT + 2 * FL_STG)        /* 87040 */

__global__ __launch_bounds__(128, 2) void flash_mma(
    const __half* __restrict__ qkv, __half* __restrict__ Ohi)
{
    extern __shared__ char smem[];
    const uint32_t sbm = smem_u32(smem);
    const uint32_t QHI = sbm;
    const uint32_t ST0 = sbm + FL_QT;

    const int qt  = (int)gridDim.x - 1 - (int)blockIdx.x;
    const int h   = blockIdx.y;
    const int kvh = h >> 2;
    const int tid = threadIdx.x, wid = tid >> 5, lane = tid & 31;
    const int qbase = qt * BQ;
    const int wm  = wid * 16;
    const int nkt = qt + 1;
    const float scale = 0.08838834764831845f;

    const int a_row = lane & 15;
    const int a_cb  = ((lane >> 4) & 1) << 3;
    const int b_row = (lane & 7) + (((lane >> 4) & 1) << 3);
    const int b_cb  = ((lane >> 3) & 1) << 3;
    const int v_row = (lane & 7) + (((lane >> 3) & 1) << 3);
    const int v_cb  = ((lane >> 4) & 1) << 3;
    const int r0    = lane >> 2;
    const int colq  = (lane & 3) * 2;

    {
        const __half* qsrc = qkv + (size_t)qbase * QKVW + h * HDIM;
#pragma unroll
        for (int it = 0; it < 8; it++) {
            int idx = tid + it * 128;
            int r = idx >> 4, c = idx & 15;
            cp16(QHI + (uint32_t)(r * FL_STR + c * 8) * 2,
                 qsrc + (size_t)r * QKVW + c * 8);
        }
        CP_COMMIT();
    }

#define FL_LOAD(s, kb) do {                                                   \
    uint32_t stb_ = ST0 + (uint32_t)(s) * FL_STG;                             \
    const __half* ksrc_ = qkv + (size_t)(kb) * QKVW + QW + kvh * HDIM;        \
    const __half* vsrc_ = ksrc_ + KWW;                                        \
    _Pragma("unroll")                                                         \
    for (int it = 0; it < 8; it++) {                                          \
        int idx = tid + it * 128;                                             \
        int r = idx >> 4, c = idx & 15;                                       \
        uint32_t d_ = (uint32_t)(r * FL_STR + c * 8) * 2;                     \
        cp16(stb_ + 0 * FL_KT + d_, ksrc_ + (size_t)r * QKVW + c * 8);        \
        cp16(stb_ + 1 * FL_KT + d_, vsrc_ + (size_t)r * QKVW + c * 8);        \
    }                                                                         \
    CP_COMMIT();                                                              \
} while (0)

    FL_LOAD(0, 0);

    uint32_t qh[8][4];
    CP_WAIT(1);
    __syncthreads();
#pragma unroll
    for (int ks = 0; ks < 8; ks++) {
        uint32_t qoff = (uint32_t)((wm + a_row) * FL_STR + ks * 16 + a_cb) * 2;
        LDSM4(qh[ks], QHI + qoff);
    }

    float l0 = 0.f, l1 = 0.f;
    float o[16][4];
#pragma unroll
    for (int j = 0; j < 16; j++)
#pragma unroll
        for (int q = 0; q < 4; q++) o[j][q] = 0.f;

    for (int kt = 0; kt < nkt; kt++) {
        if (kt + 1 < nkt) { FL_LOAD((kt + 1) & 1, (kt + 1) * BKV); CP_WAIT(1); }
        else              { CP_WAIT(0); }
        __syncthreads();

        const uint32_t stb = ST0 + (uint32_t)(kt & 1) * FL_STG;
        const uint32_t KH = stb, VH = stb + FL_KT;
        const int kbase = kt * BKV;

        float s[8][4];
#pragma unroll
        for (int j = 0; j < 8; j++)
#pragma unroll
            for (int q = 0; q < 4; q++) s[j][q] = 0.f;

#pragma unroll
        for (int ks = 0; ks < 8; ks++) {
#pragma unroll
            for (int jp = 0; jp < 4; jp++) {
                uint32_t bh[4];
                uint32_t koff = (uint32_t)((jp * 16 + b_row) * FL_STR
                                           + ks * 16 + b_cb) * 2;
                LDSM4(bh, KH + koff);
                MMA16816(s[2*jp],   qh[ks], bh);
                MMA16816(s[2*jp+1], qh[ks], bh + 2);
            }
        }

        if (kbase + BKV - 1 > qbase + wm) {
            const int row0g = qbase + wm + r0, row1g = row0g + 8;
#pragma unroll
            for (int j = 0; j < 8; j++) {
                int c0 = kbase + j * 8 + colq, c1 = c0 + 1;
                s[j][0] = (c0 <= row0g) ? __expf(s[j][0] * scale) : 0.f;
                s[j][1] = (c1 <= row0g) ? __expf(s[j][1] * scale) : 0.f;
                s[j][2] = (c0 <= row1g) ? __expf(s[j][2] * scale) : 0.f;
                s[j][3] = (c1 <= row1g) ? __expf(s[j][3] * scale) : 0.f;
                l0 += s[j][0] + s[j][1];
                l1 += s[j][2] + s[j][3];
            }
        } else {
#pragma unroll
            for (int j = 0; j < 8; j++) {
                s[j][0] = __expf(s[j][0] * scale);
                s[j][1] = __expf(s[j][1] * scale);
                s[j][2] = __expf(s[j][2] * scale);
                s[j][3] = __expf(s[j][3] * scale);
                l0 += s[j][0] + s[j][1];
                l1 += s[j][2] + s[j][3];
            }
        }

#pragma unroll
        for (int t = 0; t < 4; t++) {
            uint32_t ph[4];
            ph[0] = hpack2(s[2*t][0],   s[2*t][1]);
            ph[1] = hpack2(s[2*t][2],   s[2*t][3]);
            ph[2] = hpack2(s[2*t+1][0], s[2*t+1][1]);
            ph[3] = hpack2(s[2*t+1][2], s[2*t+1][3]);
#pragma unroll
            for (int jp = 0; jp < 8; jp++) {
                uint32_t vh[4];
                uint32_t voff = (uint32_t)((t * 16 + v_row) * FL_STR
                                           + jp * 16 + v_cb) * 2;
                LDSM4T(vh, VH + voff);
                MMA16816(o[2*jp],   ph, vh);
                MMA16816(o[2*jp+1], ph, vh + 2);
            }
        }
        __syncthreads();
    }

    l0 += __shfl_xor_sync(0xffffffffu, l0, 1);
    l0 += __shfl_xor_sync(0xffffffffu, l0, 2);
    l1 += __shfl_xor_sync(0xffffffffu, l1, 1);
    l1 += __shfl_xor_sync(0xffffffffu, l1, 2);
    const float inv0 = 1.f / l0, inv1 = 1.f / l1;
    const int row0g = qbase + wm + r0;
    const size_t base0 = (size_t)row0g * QW + h * HDIM;
    const size_t base1 = base0 + (size_t)8 * QW;
#pragma unroll
    for (int j = 0; j < 16; j++) {
        int col = j * 8 + colq;
        *(uint32_t*)(Ohi + base0 + col) = hpack2(o[j][0] * inv0, o[j][1] * inv0);
        *(uint32_t*)(Ohi + base1 + col) = hpack2(o[j][2] * inv1, o[j][3] * inv1);
    }
}

// ============================================================================
// Launch
// ============================================================================
extern "C" void kernel_launch(void* const* d_in, const int* in_sizes, int n_in,
                              void* d_out, int out_size)
{
    const float* hidden = (const float*)d_in[0];
    const float* cosT   = (const float*)d_in[1];
    const float* sinT   = (const float*)d_in[2];
    const float* wq     = (const float*)d_in[4];
    const float* wk     = (const float*)d_in[5];
    const float* wv     = (const float*)d_in[6];
    const float* wo     = (const float*)d_in[7];
    float* out = (float*)d_out;

    __half *qkv, *w_hi, *wo_hi, *a_hi;
    cudaGetSymbolAddress((void**)&qkv,   g_qkv);
    cudaGetSymbolAddress((void**)&w_hi,  g_w_hi);
    cudaGetSymbolAddress((void**)&wo_hi, g_wo_hi);
    cudaGetSymbolAddress((void**)&a_hi,  g_a_hi);

    cudaFuncSetAttribute((const void*)gemm_f16<__half, true, true>,
                         cudaFuncAttributeMaxDynamicSharedMemorySize, GEMM_SMEM);
    cudaFuncSetAttribute((const void*)gemm_f16<float, false, false>,
                         cudaFuncAttributeMaxDynamicSharedMemorySize, GEMM_SMEM);
    cudaFuncSetAttribute(flash_mma,
                         cudaFuncAttributeMaxDynamicSharedMemorySize, FLASH_SMEM);

    conv_w<<<(N_WTOT / 4 + 255) / 256, 256>>>(wq, wk, wv, wo, w_hi, wo_hi);

    gemm_f16<__half, true, true><<<dim3(QKVW / 256, SEQ / 128), 256, GEMM_SMEM>>>(
        hidden, w_hi, qkv, QKVW, DM, cosT, sinT);

    flash_mma<<<dim3(SEQ / BQ, NH), 128, FLASH_SMEM>>>(qkv, a_hi);

    gemm_f16<float, false, false><<<dim3(DM / 256, SEQ / 128), 256, GEMM_SMEM>>>(
        a_hi, wo_hi, out, DM, DM, nullptr, nullptr);
}